// round 2
// baseline (speedup 1.0000x reference)
#include <cuda_runtime.h>
#include <cuda_bf16.h>
#include <math.h>

// Problem constants
#define BB 1024   // batch
#define II 256    // in features
#define OO 256    // out features
#define KK 128    // knots

// Main-kernel tiling
#define OT 32          // o per CTA (one per lane)
#define BT 512         // b per CTA
#define NWARP 16       // 512 threads
#define NICHUNK 16     // i-chunks in grid
#define IPC (II / NICHUNK)  // 16 i per chunk
#define CPAD 129       // padded row stride (floats) for conflict-free gathers

// Scratch: meta[i][b] = {frac, (l*4) as float-bits, silu, unused}
__device__ float4 g_meta[II * BB];   // 4 MB

// ---------------------------------------------------------------------------
// Kernel 1: per-element activation / knot prep, written transposed [i][b]
// ---------------------------------------------------------------------------
__global__ void kan_prep(const float* __restrict__ x) {
    __shared__ float4 sm[32][33];
    int i = blockIdx.x * 32 + threadIdx.x;
    int b = blockIdx.y * 32 + threadIdx.y;

    float xv = x[b * II + i];
    float p = tanhf(xv);
    float sig = 1.0f / (1.0f + expf(-p));
    float silu = p * sig;
    float c = fminf(fmaxf(p, -1.0f), 1.0f);
    float scaled = (c + 1.0f) * 63.5f;          // (c - DMIN)/step, step = 2/127
    int l = (int)scaled;
    if (l > 126) l = 126;                       // right = l+1 always valid
    float frac = scaled - (float)l;

    sm[threadIdx.y][threadIdx.x] = make_float4(frac, __int_as_float(l * 4), silu, 0.0f);
    __syncthreads();

    int i2 = blockIdx.x * 32 + threadIdx.y;
    int b2 = blockIdx.y * 32 + threadIdx.x;
    g_meta[i2 * BB + b2] = sm[threadIdx.x][threadIdx.y];  // coalesced over b2
}

// ---------------------------------------------------------------------------
// Kernel 2: out[b,o] = bias[o]  (out arrives poisoned)
// ---------------------------------------------------------------------------
__global__ void kan_init(const float* __restrict__ bias, float* __restrict__ out) {
    int idx = blockIdx.x * blockDim.x + threadIdx.x;  // b*OO + o
    out[idx] = bias[idx & (OO - 1)];
}

// ---------------------------------------------------------------------------
// Kernel 3: spline gather-accumulate + base GEMM folded in, atomic reduce
// grid = (NICHUNK, BB/BT, OO/OT), block = 512
// ---------------------------------------------------------------------------
__global__ __launch_bounds__(512, 2)
void kan_spline(const float* __restrict__ coeff,   // [O][I][K]
                const float* __restrict__ scale,   // [O][I]
                const float* __restrict__ bw,      // [O][I]
                float* __restrict__ out) {         // [B][O]
    __shared__ float  ctile[OT * CPAD];            // 16.5 KB, scaled coeff slice
    __shared__ float4 mtile[BT];                   // 8 KB, meta for this i
    __shared__ float  wtile[OT * 17];              // 2.2 KB, W[o, i-chunk], pad 17

    const int tid  = threadIdx.x;
    const int lane = tid & 31;
    const int warp = tid >> 5;
    const int o0 = blockIdx.z * OT;
    const int b0 = blockIdx.y * BT;
    const int i0 = blockIdx.x * IPC;

    // preload base-weight tile: wtile[o][ii] = bw[o0+o][i0+ii]
    {
        int o  = tid >> 4;      // 0..31
        int ii = tid & 15;      // 0..15
        wtile[o * 17 + ii] = bw[(size_t)(o0 + o) * II + i0 + ii];
    }

    float acc[32];
#pragma unroll
    for (int j = 0; j < 32; j++) acc[j] = 0.0f;

    const int myo = o0 + lane;
    const float* myrow = ctile + lane * CPAD;
    const int lo = tid >> 4;   // loader: o row 0..31
    const int ls = tid & 15;   // loader: float4 segment 0..15

    for (int ii = 0; ii < IPC; ii++) {
        const int i = i0 + ii;
        __syncthreads();   // protect ctile/mtile from previous iteration readers
        {
            const float4* src = (const float4*)(coeff + ((size_t)(o0 + lo) * II + i) * KK);
            float sc = scale[(size_t)(o0 + lo) * II + i];
            float4 v0 = src[ls];
            float4 v1 = src[ls + 16];
            float* drow = ctile + lo * CPAD;
            int c0 = ls * 4;
            drow[c0 + 0]  = v0.x * sc;  drow[c0 + 1]  = v0.y * sc;
            drow[c0 + 2]  = v0.z * sc;  drow[c0 + 3]  = v0.w * sc;
            drow[c0 + 64] = v1.x * sc;  drow[c0 + 65] = v1.y * sc;
            drow[c0 + 66] = v1.z * sc;  drow[c0 + 67] = v1.w * sc;
            mtile[tid] = g_meta[(size_t)i * BB + b0 + tid];
        }
        float wreg = wtile[lane * 17 + ii];   // W[myo][i], conflict-free (odd stride)
        __syncthreads();

#pragma unroll
        for (int bb = 0; bb < 32; bb++) {
            float4 m = mtile[warp * 32 + bb];                 // broadcast
            int loff = __float_as_int(m.y);                   // l*4 bytes
            float cl = *(const float*)((const char*)myrow + loff);
            float cr = *(const float*)((const char*)myrow + loff + 4);
            float f  = m.x;
            float a  = acc[bb];
            a = fmaf(m.z, wreg, a);        // base: silu * W[o,i]
            a = fmaf(1.0f - f, cl, a);     // spline left
            a = fmaf(f, cr, a);            // spline right
            acc[bb] = a;
        }
    }

    float* op = out + (size_t)(b0 + warp * 32) * OO + myo;
#pragma unroll
    for (int bb = 0; bb < 32; bb++)
        atomicAdd(op + (size_t)bb * OO, acc[bb]);
}

// ---------------------------------------------------------------------------
// Launch
// ---------------------------------------------------------------------------
extern "C" void kernel_launch(void* const* d_in, const int* in_sizes, int n_in,
                              void* d_out, int out_size) {
    const float* x     = (const float*)d_in[0];  // [B][I]
    const float* bw    = (const float*)d_in[1];  // [O][I]
    const float* coeff = (const float*)d_in[2];  // [O][I][K]
    const float* scale = (const float*)d_in[3];  // [O][I]
    const float* bias  = (const float*)d_in[4];  // [O]
    float* out = (float*)d_out;                  // [B][O]

    kan_prep<<<dim3(II / 32, BB / 32), dim3(32, 32)>>>(x);
    kan_init<<<(BB * OO) / 256, 256>>>(bias, out);
    kan_spline<<<dim3(NICHUNK, BB / BT, OO / OT), 512>>>(coeff, scale, bw, out);
}